// round 6
// baseline (speedup 1.0000x reference)
#include <cuda_runtime.h>
#include <cuda_bf16.h>
#include <cstdint>

#define NN 50000
#define EE 800000
#define DIM 256

// ---- scratch (static device globals) ----
__device__ __nv_bfloat16 d_h[(size_t)NN * DIM];   // 25.6 MB
__device__ __nv_bfloat16 d_a[(size_t)NN * DIM];   // 25.6 MB
__device__ int   d_degi[NN];
__device__ float d_dinv[NN];
__device__ float d_mean[DIM];
__device__ int   d_rowstart[NN + 1];
__device__ int   d_cursor[NN];
__device__ int   d_csr[EE];
__device__ float d_wp1[65536];   // W1 in mma-fragment order (tf32)
__device__ float d_wp2[65536];   // W2 in mma-fragment order (tf32)

// ---------------- degree ----------------
__global__ void k_deg(const int* __restrict__ dst, int E, int* __restrict__ deg) {
    int e = blockIdx.x * blockDim.x + threadIdx.x;
    if (e < E) atomicAdd(&deg[dst[e]], 1);
}

// ---------------- fused scan: rowstart + cursor + dinv ----------------
__global__ void k_scan(const int* __restrict__ deg, int* __restrict__ rowstart,
                       int* __restrict__ cursor, float* __restrict__ dinv, int n) {
    __shared__ int partial[1024];
    int t = threadIdx.x;
    int chunk = (n + 1023) >> 10;
    int beg = t * chunk;
    int end = min(beg + chunk, n);
    int s = 0;
    for (int i = beg; i < end; i++) s += deg[i];
    partial[t] = s;
    __syncthreads();
    for (int off = 1; off < 1024; off <<= 1) {
        int add = (t >= off) ? partial[t - off] : 0;
        __syncthreads();
        partial[t] += add;
        __syncthreads();
    }
    int excl = (t == 0) ? 0 : partial[t - 1];
    for (int i = beg; i < end; i++) {
        rowstart[i] = excl;
        cursor[i] = excl;
        dinv[i] = rsqrtf((float)deg[i] + 1.0f);   // +1 = self loop
        excl += deg[i];
    }
    if (end == n) rowstart[n] = excl;
}

// ---------------- CSR fill ----------------
__global__ void k_fill(const int* __restrict__ src, const int* __restrict__ dst,
                       int* __restrict__ cursor, int* __restrict__ csr, int E) {
    int e = blockIdx.x * blockDim.x + threadIdx.x;
    if (e < E) {
        int pos = atomicAdd(&cursor[dst[e]], 1);
        csr[pos] = src[e];
    }
}

// ---------------- B permute: W[256,256] -> fragment-ordered Wp (tf32) ----------------
// Wp[((((k0t*2+nb)*4+kk)*4+wn)*2+ntp)*128 + lane*4 + sub]
//   sub: (nt within pair)<<1 | pair;  k = k0t*32+kk*8+ti+pair*4;
//   col = nb*128 + wn*32 + (2*ntp + (sub>>1))*8 + gi
__global__ void k_permB(const float* __restrict__ W, float* __restrict__ Wp) {
    int t = blockIdx.x * blockDim.x + threadIdx.x;
    if (t >= 65536) return;
    int sub  = t & 3;
    int lane = (t >> 2) & 31;
    int ntp  = (t >> 7) & 1;
    int wn   = (t >> 8) & 3;
    int kk   = (t >> 10) & 3;
    int nb   = (t >> 12) & 1;
    int k0t  = (t >> 13) & 7;
    int gi = lane >> 2, ti = lane & 3;
    int nt = ntp * 2 + (sub >> 1);
    int pair = sub & 1;
    int k = k0t * 32 + kk * 8 + ti + pair * 4;
    int col = nb * 128 + wn * 32 + nt * 8 + gi;
    unsigned u;
    asm("cvt.rna.tf32.f32 %0, %1;" : "=r"(u) : "f"(W[k * 256 + col]));
    Wp[t] = __uint_as_float(u);
}

// ---------------- TF32 GEMM: A-smem k-permuted (LDS.128 frags), B from Wp (LDG.128) ----
// As position for value k (0..31): p = (k%4)*8 + k/4, row stride 36 words.
template <bool BF16IN>
__global__ void __launch_bounds__(256, 2)
k_gemm(const void* __restrict__ Aptr, const float* __restrict__ Wp,
       __nv_bfloat162* __restrict__ C, int M) {
    __shared__ float As[2][128 * 36];
    int t = threadIdx.x;
    int lane = t & 31, wid = t >> 5;
    int wm = wid & 1, wn = wid >> 1;          // warp tile: 64x32
    int gi = lane >> 2, ti = lane & 3;
    int m0 = blockIdx.y * 128, nb = blockIdx.x;

    float acc[4][4][4] = {};
    float4 stg[4];
    uint4  stgh[2];

    auto ldgTile = [&](int k0) {
        if (BF16IN) {
            const __nv_bfloat16* A = (const __nv_bfloat16*)Aptr;
            #pragma unroll
            for (int i = 0; i < 2; i++) {
                int g = t + i * 256;
                int ar = g >> 2, j8 = g & 3;
                int row = m0 + ar;
                stgh[i] = (row < M)
                    ? *(const uint4*)(A + (size_t)row * 256 + k0 + j8 * 8)
                    : make_uint4(0, 0, 0, 0);
            }
        } else {
            const float* A = (const float*)Aptr;
            #pragma unroll
            for (int i = 0; i < 4; i++) {
                int g = t + i * 256;
                int ar = g >> 3, j = g & 7;
                int row = m0 + ar;
                stg[i] = (row < M)
                    ? *(const float4*)(A + (size_t)row * 256 + k0 + j * 4)
                    : make_float4(0.f, 0.f, 0.f, 0.f);
            }
        }
    };
    auto stsTile = [&](int st) {
        float* S = As[st];
        if (BF16IN) {
            #pragma unroll
            for (int i = 0; i < 2; i++) {
                int g = t + i * 256;
                int ar = g >> 2, j8 = g & 3;
                const __nv_bfloat162* p = (const __nv_bfloat162*)&stgh[i];
                #pragma unroll
                for (int c = 0; c < 4; c++) {
                    // f0 = elem m=c, f1 = elem m=c+4 (k = 8*j8 + m)
                    float2 lo = __bfloat1622float2(p[c >> 1]);
                    float2 hi = __bfloat1622float2(p[(c >> 1) + 2]);
                    float f0 = (c & 1) ? lo.y : lo.x;
                    float f1 = (c & 1) ? hi.y : hi.x;
                    *(float2*)&S[ar * 36 + c * 8 + 2 * j8] = make_float2(f0, f1);
                }
            }
        } else {
            #pragma unroll
            for (int i = 0; i < 4; i++) {
                int g = t + i * 256;
                int ar = g >> 3, j = g & 7;
                const float* v = (const float*)&stg[i];
                #pragma unroll
                for (int c = 0; c < 4; c++) {
                    unsigned u;
                    asm("cvt.rna.tf32.f32 %0, %1;" : "=r"(u) : "f"(v[c]));
                    S[ar * 36 + c * 8 + j] = __uint_as_float(u);
                }
            }
        }
    };
    auto compute = [&](int st, int k0t) {
        const float* S = As[st];
        const float* WpB = Wp + (size_t)(k0t * 2 + nb) * 4096;
        #pragma unroll
        for (int half = 0; half < 2; half++) {
            float4 af[4][2];
            #pragma unroll
            for (int mt = 0; mt < 4; mt++) {
                int r = wm * 64 + mt * 16 + gi;
                af[mt][0] = *(const float4*)&S[r * 36 + ti * 8 + half * 4];
                af[mt][1] = *(const float4*)&S[(r + 8) * 36 + ti * 8 + half * 4];
            }
            #pragma unroll
            for (int kkh = 0; kkh < 2; kkh++) {
                int kk = half * 2 + kkh;
                #pragma unroll
                for (int ntp = 0; ntp < 2; ntp++) {
                    float4 b4 = *(const float4*)(WpB +
                        (size_t)((kk * 4 + wn) * 2 + ntp) * 128 + lane * 4);
                    unsigned bx = __float_as_uint(b4.x), by = __float_as_uint(b4.y);
                    unsigned bz = __float_as_uint(b4.z), bw = __float_as_uint(b4.w);
                    #pragma unroll
                    for (int mt = 0; mt < 4; mt++) {
                        const float* a0 = (const float*)&af[mt][0];
                        const float* a1 = (const float*)&af[mt][1];
                        unsigned aa0 = __float_as_uint(a0[2 * kkh]);
                        unsigned aa1 = __float_as_uint(a1[2 * kkh]);
                        unsigned aa2 = __float_as_uint(a0[2 * kkh + 1]);
                        unsigned aa3 = __float_as_uint(a1[2 * kkh + 1]);
                        int nt0 = ntp * 2;
                        asm volatile(
                            "mma.sync.aligned.m16n8k8.row.col.f32.tf32.tf32.f32 "
                            "{%0,%1,%2,%3}, {%4,%5,%6,%7}, {%8,%9}, {%0,%1,%2,%3};"
                            : "+f"(acc[mt][nt0][0]), "+f"(acc[mt][nt0][1]),
                              "+f"(acc[mt][nt0][2]), "+f"(acc[mt][nt0][3])
                            : "r"(aa0), "r"(aa1), "r"(aa2), "r"(aa3),
                              "r"(bx), "r"(by));
                        asm volatile(
                            "mma.sync.aligned.m16n8k8.row.col.f32.tf32.tf32.f32 "
                            "{%0,%1,%2,%3}, {%4,%5,%6,%7}, {%8,%9}, {%0,%1,%2,%3};"
                            : "+f"(acc[mt][nt0 + 1][0]), "+f"(acc[mt][nt0 + 1][1]),
                              "+f"(acc[mt][nt0 + 1][2]), "+f"(acc[mt][nt0 + 1][3])
                            : "r"(aa0), "r"(aa1), "r"(aa2), "r"(aa3),
                              "r"(bz), "r"(bw));
                    }
                }
            }
        }
    };

    ldgTile(0);
    stsTile(0);
    __syncthreads();
    for (int i = 0; i < 8; i++) {
        if (i < 7) ldgTile((i + 1) * 32);
        compute(i & 1, i);
        if (i < 7) {
            __syncthreads();
            stsTile((i + 1) & 1);
            __syncthreads();
        }
    }

    #pragma unroll
    for (int mt = 0; mt < 4; mt++)
        #pragma unroll
        for (int nt = 0; nt < 4; nt++) {
            int row = m0 + wm * 64 + mt * 16 + gi;
            int pc = nb * 64 + wn * 16 + nt * 4 + ti;
            if (row < M)
                C[(size_t)row * 128 + pc] =
                    __floats2bfloat162_rn(acc[mt][nt][0], acc[mt][nt][1]);
            if (row + 8 < M)
                C[(size_t)(row + 8) * 128 + pc] =
                    __floats2bfloat162_rn(acc[mt][nt][2], acc[mt][nt][3]);
        }
}

// ---------------- gather helpers (packed f32x2) ----------------
__device__ __forceinline__ unsigned long long bf2f2(unsigned u) {
    unsigned lo = u << 16, hi = u & 0xffff0000u;
    unsigned long long r;
    asm("mov.b64 %0, {%1,%2};" : "=l"(r) : "r"(lo), "r"(hi));
    return r;
}
__device__ __forceinline__ unsigned long long packf2(float w) {
    unsigned long long r;
    asm("mov.b64 %0, {%1,%1};" : "=l"(r) : "f"(w));
    return r;
}
__device__ __forceinline__ void fma2(unsigned long long& acc,
                                     unsigned long long v, unsigned long long w) {
    asm("fma.rn.f32x2 %0, %1, %2, %0;" : "+l"(acc) : "l"(v), "l"(w));
}
__device__ __forceinline__ void row_fma(const uint4* __restrict__ H, int s, int lane,
                                        unsigned long long w2, unsigned long long* acc) {
    uint4 v = H[(size_t)s * 32 + lane];
    fma2(acc[0], bf2f2(v.x), w2);
    fma2(acc[1], bf2f2(v.y), w2);
    fma2(acc[2], bf2f2(v.z), w2);
    fma2(acc[3], bf2f2(v.w), w2);
}

// Per-node gather: lanes preload up to 32 neighbor (idx, w), broadcast via shfl,
// 4 independent row loads in flight per unrolled step.
__device__ __forceinline__ void gather_node(const uint4* __restrict__ H,
        const int* __restrict__ rowstart, const int* __restrict__ csr,
        const float* __restrict__ dinv, const float* __restrict__ bias,
        int node, int lane, float di, float* res) {
    int r0 = rowstart[node], r1 = rowstart[node + 1];
    unsigned long long acc[4] = {0ull, 0ull, 0ull, 0ull};
    row_fma(H, node, lane, packf2(di), acc);   // self loop
    for (int base = r0; base < r1; base += 32) {
        int cnt = min(32, r1 - base);
        int s = 0; float w = 0.f;
        if (base + lane < r1) { s = csr[base + lane]; w = dinv[s]; }
        int j = 0;
        for (; j + 4 <= cnt; j += 4) {
            int s0 = __shfl_sync(0xffffffffu, s, j);
            int s1 = __shfl_sync(0xffffffffu, s, j + 1);
            int s2 = __shfl_sync(0xffffffffu, s, j + 2);
            int s3 = __shfl_sync(0xffffffffu, s, j + 3);
            float w0 = __shfl_sync(0xffffffffu, w, j);
            float w1 = __shfl_sync(0xffffffffu, w, j + 1);
            float w2 = __shfl_sync(0xffffffffu, w, j + 2);
            float w3 = __shfl_sync(0xffffffffu, w, j + 3);
            row_fma(H, s0, lane, packf2(w0), acc);
            row_fma(H, s1, lane, packf2(w1), acc);
            row_fma(H, s2, lane, packf2(w2), acc);
            row_fma(H, s3, lane, packf2(w3), acc);
        }
        for (; j < cnt; j++) {
            int sj = __shfl_sync(0xffffffffu, s, j);
            float wj = __shfl_sync(0xffffffffu, w, j);
            row_fma(H, sj, lane, packf2(wj), acc);
        }
    }
    float4 b0 = *(const float4*)(bias + lane * 8);
    float4 b1 = *(const float4*)(bias + lane * 8 + 4);
    float bb[8] = {b0.x, b0.y, b0.z, b0.w, b1.x, b1.y, b1.z, b1.w};
    #pragma unroll
    for (int jj = 0; jj < 4; jj++) {
        float x0, x1;
        asm("mov.b64 {%0,%1}, %2;" : "=f"(x0), "=f"(x1) : "l"(acc[jj]));
        res[2 * jj]     = fmaxf(fmaf(di, x0, bb[2 * jj]),     0.f);
        res[2 * jj + 1] = fmaxf(fmaf(di, x1, bb[2 * jj + 1]), 0.f);
    }
}

// ---------------- gather 1: write bf16 activations ----------------
__global__ void k_gather1(const uint4* __restrict__ H, uint4* __restrict__ out,
                          const int* __restrict__ rowstart, const int* __restrict__ csr,
                          const float* __restrict__ dinv,
                          const float* __restrict__ bias, int n) {
    int node = blockIdx.x * 8 + (threadIdx.x >> 5);
    if (node >= n) return;
    int lane = threadIdx.x & 31;
    float res[8];
    gather_node(H, rowstart, csr, dinv, bias, node, lane, dinv[node], res);
    __nv_bfloat162 r[4];
    #pragma unroll
    for (int j = 0; j < 4; j++)
        r[j] = __floats2bfloat162_rn(res[2 * j], res[2 * j + 1]);
    out[(size_t)node * 32 + lane] = *(uint4*)r;
}

// ---------------- gather 2: reduce directly into mean ----------------
__global__ void k_gather2(const uint4* __restrict__ H,
                          const int* __restrict__ rowstart, const int* __restrict__ csr,
                          const float* __restrict__ dinv,
                          const float* __restrict__ bias,
                          float* __restrict__ mean, int n) {
    __shared__ float sm[8][256];
    int warp = threadIdx.x >> 5;
    int lane = threadIdx.x & 31;
    int node = blockIdx.x * 8 + warp;
    float res[8] = {};
    if (node < n)
        gather_node(H, rowstart, csr, dinv, bias, node, lane, dinv[node], res);
    #pragma unroll
    for (int j = 0; j < 8; j++) sm[warp][lane * 8 + j] = res[j];
    __syncthreads();
    int c = threadIdx.x;
    float s = 0.f;
    #pragma unroll
    for (int w = 0; w < 8; w++) s += sm[w][c];
    atomicAdd(&mean[c], s);
}

// ---------------- MLP head ----------------
__global__ void k_head(const float* __restrict__ mean,
                       const float* __restrict__ fcW1, const float* __restrict__ fcb1,
                       const float* __restrict__ fcW2, const float* __restrict__ fcb2,
                       const float* __restrict__ fcW3, const float* __restrict__ fcb3,
                       float* __restrict__ out, int n) {
    __shared__ float g[256], h[256];
    int j = threadIdx.x;
    g[j] = fmaxf(mean[j] * (1.0f / (float)n), 0.f);
    __syncthreads();
    float s = fcb1[j];
    #pragma unroll 8
    for (int i = 0; i < 256; i++) s = fmaf(g[i], fcW1[i * 256 + j], s);
    h[j] = fmaxf(s, 0.f);
    __syncthreads();
    s = fcb2[j];
    #pragma unroll 8
    for (int i = 0; i < 256; i++) s = fmaf(h[i], fcW2[i * 256 + j], s);
    float g2 = fmaxf(s, 0.f);
    __syncthreads();
    g[j] = g2;
    __syncthreads();
    if (j < 64) {
        s = fcb3[j];
        #pragma unroll 8
        for (int i = 0; i < 256; i++) s = fmaf(g[i], fcW3[i * 64 + j], s);
        out[j] = s;
    }
}

extern "C" void kernel_launch(void* const* d_in, const int* in_sizes, int n_in,
                              void* d_out, int out_size) {
    const float* x    = (const float*)d_in[0];
    const int*   ei   = (const int*)  d_in[1];   // [2, E] int32
    const float* W1   = (const float*)d_in[2];
    const float* b1   = (const float*)d_in[3];
    const float* W2   = (const float*)d_in[4];
    const float* b2   = (const float*)d_in[5];
    const float* fcW1 = (const float*)d_in[6];
    const float* fcb1 = (const float*)d_in[7];
    const float* fcW2 = (const float*)d_in[8];
    const float* fcb2 = (const float*)d_in[9];
    const float* fcW3 = (const float*)d_in[10];
    const float* fcb3 = (const float*)d_in[11];
    float* out = (float*)d_out;

    int E = in_sizes[1] / 2;
    int N = in_sizes[0] / DIM;
    const int* src = ei;
    const int* dst = ei + E;

    __nv_bfloat16 *hbuf, *abuf;
    float *dinv, *mean, *wp1, *wp2;
    int *degi, *rowstart, *cursor, *csr;
    cudaGetSymbolAddress((void**)&hbuf, d_h);
    cudaGetSymbolAddress((void**)&abuf, d_a);
    cudaGetSymbolAddress((void**)&degi, d_degi);
    cudaGetSymbolAddress((void**)&dinv, d_dinv);
    cudaGetSymbolAddress((void**)&mean, d_mean);
    cudaGetSymbolAddress((void**)&rowstart, d_rowstart);
    cudaGetSymbolAddress((void**)&cursor, d_cursor);
    cudaGetSymbolAddress((void**)&csr, d_csr);
    cudaGetSymbolAddress((void**)&wp1, d_wp1);
    cudaGetSymbolAddress((void**)&wp2, d_wp2);

    // side stream + events (created once; host-side resources only)
    static cudaStream_t s_side = nullptr;
    static cudaEvent_t ev_fork = nullptr, ev_join = nullptr;
    if (s_side == nullptr) {
        cudaStreamCreateWithFlags(&s_side, cudaStreamNonBlocking);
        cudaEventCreateWithFlags(&ev_fork, cudaEventDisableTiming);
        cudaEventCreateWithFlags(&ev_join, cudaEventDisableTiming);
    }

    dim3 gg(2, (N + 127) / 128);
    unsigned gblocks = (unsigned)((N + 7) / 8);

    // ---- fork: W2 permute + CSR build on side stream, concurrent with GEMM-1 ----
    cudaEventRecord(ev_fork, 0);
    cudaStreamWaitEvent(s_side, ev_fork, 0);
    k_permB<<<256, 256, 0, s_side>>>(W2, wp2);
    cudaMemsetAsync(degi, 0, (size_t)N * sizeof(int), s_side);
    k_deg<<<(E + 255) / 256, 256, 0, s_side>>>(dst, E, degi);
    k_scan<<<1, 1024, 0, s_side>>>(degi, rowstart, cursor, dinv, N);
    k_fill<<<(E + 255) / 256, 256, 0, s_side>>>(src, dst, cursor, csr, E);
    cudaEventRecord(ev_join, s_side);

    // main stream: W1 permute, GEMM-1, mean clear
    cudaMemsetAsync(mean, 0, DIM * sizeof(float));
    k_permB<<<256, 256>>>(W1, wp1);
    k_gemm<false><<<gg, 256>>>(x, wp1, (__nv_bfloat162*)hbuf, N);

    // join before the gather needs the CSR (and before gemm2 needs wp2)
    cudaStreamWaitEvent(0, ev_join, 0);

    // ---- layer 1 aggregation ----
    k_gather1<<<gblocks, 256>>>((const uint4*)hbuf, (uint4*)abuf,
                                rowstart, csr, dinv, b1, N);
    // ---- layer 2 (mean fused into gather) ----
    k_gemm<true><<<gg, 256>>>(abuf, wp2, (__nv_bfloat162*)hbuf, N);
    k_gather2<<<gblocks, 256>>>((const uint4*)hbuf, rowstart, csr, dinv, b2,
                                mean, N);
    // ---- head ----
    k_head<<<1, 256>>>(mean, fcW1, fcb1, fcW2, fcb2, fcW3, fcb3, out, N);
}

// round 7
// speedup vs baseline: 1.0491x; 1.0491x over previous
#include <cuda_runtime.h>
#include <cuda_bf16.h>
#include <cstdint>

#define NN 50000
#define EE 800000
#define DIM 256

// ---- scratch (static device globals) ----
__device__ __nv_bfloat16 d_h[(size_t)NN * DIM];   // 25.6 MB
__device__ __nv_bfloat16 d_a[(size_t)NN * DIM];   // 25.6 MB
__device__ int   d_degi[NN];
__device__ float d_dinv[NN];
__device__ float d_mean[DIM];
__device__ int   d_rowstart[NN + 1];
__device__ int   d_cursor[NN];
__device__ int   d_csr[EE];
__device__ float d_wp1[65536];   // W1 in mma-fragment order (tf32)
__device__ float d_wp2[65536];   // W2 in mma-fragment order (tf32)

// ---------------- degree ----------------
__global__ void k_deg(const int* __restrict__ dst, int E, int* __restrict__ deg) {
    int e = blockIdx.x * blockDim.x + threadIdx.x;
    if (e < E) atomicAdd(&deg[dst[e]], 1);
}

// ---------------- fused scan: rowstart + cursor + dinv ----------------
__global__ void k_scan(const int* __restrict__ deg, int* __restrict__ rowstart,
                       int* __restrict__ cursor, float* __restrict__ dinv, int n) {
    __shared__ int partial[1024];
    int t = threadIdx.x;
    int chunk = (n + 1023) >> 10;
    int beg = t * chunk;
    int end = min(beg + chunk, n);
    int s = 0;
    for (int i = beg; i < end; i++) s += deg[i];
    partial[t] = s;
    __syncthreads();
    for (int off = 1; off < 1024; off <<= 1) {
        int add = (t >= off) ? partial[t - off] : 0;
        __syncthreads();
        partial[t] += add;
        __syncthreads();
    }
    int excl = (t == 0) ? 0 : partial[t - 1];
    for (int i = beg; i < end; i++) {
        rowstart[i] = excl;
        cursor[i] = excl;
        dinv[i] = rsqrtf((float)deg[i] + 1.0f);   // +1 = self loop
        excl += deg[i];
    }
    if (end == n) rowstart[n] = excl;
}

// ---------------- CSR fill ----------------
__global__ void k_fill(const int* __restrict__ src, const int* __restrict__ dst,
                       int* __restrict__ cursor, int* __restrict__ csr, int E) {
    int e = blockIdx.x * blockDim.x + threadIdx.x;
    if (e < E) {
        int pos = atomicAdd(&cursor[dst[e]], 1);
        csr[pos] = src[e];
    }
}

// ---------------- B permute: W[256,256] -> fragment-ordered Wp (tf32) ----------------
// (verified correct in round 6)
__global__ void k_permB(const float* __restrict__ W, float* __restrict__ Wp) {
    int t = blockIdx.x * blockDim.x + threadIdx.x;
    if (t >= 65536) return;
    int sub  = t & 3;
    int lane = (t >> 2) & 31;
    int ntp  = (t >> 7) & 1;
    int wn   = (t >> 8) & 3;
    int kk   = (t >> 10) & 3;
    int nb   = (t >> 12) & 1;
    int k0t  = (t >> 13) & 7;
    int gi = lane >> 2, ti = lane & 3;
    int nt = ntp * 2 + (sub >> 1);
    int pair = sub & 1;
    int k = k0t * 32 + kk * 8 + ti + pair * 4;
    int col = nb * 128 + wn * 32 + nt * 8 + gi;
    unsigned u;
    asm("cvt.rna.tf32.f32 %0, %1;" : "=r"(u) : "f"(W[k * 256 + col]));
    Wp[t] = __uint_as_float(u);
}

// ---------------- TF32 GEMM: k-permuted A-smem (LDS.64 frags), B from Wp (LDG.128) ----
// As value k at p = (k%4)*8 + k/4, row stride 36 words. Fragments streamed per-kk.
template <bool BF16IN>
__global__ void __launch_bounds__(256, 2)
k_gemm(const void* __restrict__ Aptr, const float* __restrict__ Wp,
       __nv_bfloat162* __restrict__ C, int M) {
    __shared__ float As[2][128 * 36];
    int t = threadIdx.x;
    int lane = t & 31, wid = t >> 5;
    int wm = wid & 1, wn = wid >> 1;          // warp tile: 64x32
    int gi = lane >> 2, ti = lane & 3;
    int m0 = blockIdx.y * 128, nb = blockIdx.x;

    float acc[4][4][4] = {};
    float4 stg[4];
    uint4  stgh[2];

    auto ldgTile = [&](int k0) {
        if (BF16IN) {
            const __nv_bfloat16* A = (const __nv_bfloat16*)Aptr;
            #pragma unroll
            for (int i = 0; i < 2; i++) {
                int g = t + i * 256;
                int ar = g >> 2, j8 = g & 3;
                int row = m0 + ar;
                stgh[i] = (row < M)
                    ? *(const uint4*)(A + (size_t)row * 256 + k0 + j8 * 8)
                    : make_uint4(0, 0, 0, 0);
            }
        } else {
            const float* A = (const float*)Aptr;
            #pragma unroll
            for (int i = 0; i < 4; i++) {
                int g = t + i * 256;
                int ar = g >> 3, j = g & 7;
                int row = m0 + ar;
                stg[i] = (row < M)
                    ? *(const float4*)(A + (size_t)row * 256 + k0 + j * 4)
                    : make_float4(0.f, 0.f, 0.f, 0.f);
            }
        }
    };
    auto stsTile = [&](int st) {
        float* S = As[st];
        if (BF16IN) {
            #pragma unroll
            for (int i = 0; i < 2; i++) {
                int g = t + i * 256;
                int ar = g >> 2, j8 = g & 3;
                const __nv_bfloat162* p = (const __nv_bfloat162*)&stgh[i];
                #pragma unroll
                for (int c = 0; c < 4; c++) {
                    float2 lo = __bfloat1622float2(p[c >> 1]);
                    float2 hi = __bfloat1622float2(p[(c >> 1) + 2]);
                    float f0 = (c & 1) ? lo.y : lo.x;
                    float f1 = (c & 1) ? hi.y : hi.x;
                    *(float2*)&S[ar * 36 + c * 8 + 2 * j8] = make_float2(f0, f1);
                }
            }
        } else {
            #pragma unroll
            for (int i = 0; i < 4; i++) {
                int g = t + i * 256;
                int ar = g >> 3, j = g & 7;
                const float* v = (const float*)&stg[i];
                #pragma unroll
                for (int c = 0; c < 4; c++) {
                    unsigned u;
                    asm("cvt.rna.tf32.f32 %0, %1;" : "=r"(u) : "f"(v[c]));
                    S[ar * 36 + c * 8 + j] = __uint_as_float(u);
                }
            }
        }
    };
    auto compute = [&](int st, int k0t) {
        const float* S = As[st];
        const float* WpB = Wp + (size_t)(k0t * 2 + nb) * 4096;
        #pragma unroll
        for (int kk = 0; kk < 4; kk++) {
            float4 bA = *(const float4*)(WpB +
                (size_t)((kk * 4 + wn) * 2 + 0) * 128 + lane * 4);
            float4 bB = *(const float4*)(WpB +
                (size_t)((kk * 4 + wn) * 2 + 1) * 128 + lane * 4);
            unsigned bAx = __float_as_uint(bA.x), bAy = __float_as_uint(bA.y);
            unsigned bAz = __float_as_uint(bA.z), bAw = __float_as_uint(bA.w);
            unsigned bBx = __float_as_uint(bB.x), bBy = __float_as_uint(bB.y);
            unsigned bBz = __float_as_uint(bB.z), bBw = __float_as_uint(bB.w);
            #pragma unroll
            for (int mt = 0; mt < 4; mt++) {
                int r = wm * 64 + mt * 16 + gi;
                float2 lo = *(const float2*)&S[r * 36 + ti * 8 + 2 * kk];
                float2 hi = *(const float2*)&S[(r + 8) * 36 + ti * 8 + 2 * kk];
                unsigned a0 = __float_as_uint(lo.x);   // A[gi][k]
                unsigned a1 = __float_as_uint(hi.x);   // A[gi+8][k]
                unsigned a2 = __float_as_uint(lo.y);   // A[gi][k+4]
                unsigned a3 = __float_as_uint(hi.y);   // A[gi+8][k+4]
                asm volatile(
                    "mma.sync.aligned.m16n8k8.row.col.f32.tf32.tf32.f32 "
                    "{%0,%1,%2,%3}, {%4,%5,%6,%7}, {%8,%9}, {%0,%1,%2,%3};"
                    : "+f"(acc[mt][0][0]), "+f"(acc[mt][0][1]),
                      "+f"(acc[mt][0][2]), "+f"(acc[mt][0][3])
                    : "r"(a0), "r"(a1), "r"(a2), "r"(a3), "r"(bAx), "r"(bAy));
                asm volatile(
                    "mma.sync.aligned.m16n8k8.row.col.f32.tf32.tf32.f32 "
                    "{%0,%1,%2,%3}, {%4,%5,%6,%7}, {%8,%9}, {%0,%1,%2,%3};"
                    : "+f"(acc[mt][1][0]), "+f"(acc[mt][1][1]),
                      "+f"(acc[mt][1][2]), "+f"(acc[mt][1][3])
                    : "r"(a0), "r"(a1), "r"(a2), "r"(a3), "r"(bAz), "r"(bAw));
                asm volatile(
                    "mma.sync.aligned.m16n8k8.row.col.f32.tf32.tf32.f32 "
                    "{%0,%1,%2,%3}, {%4,%5,%6,%7}, {%8,%9}, {%0,%1,%2,%3};"
                    : "+f"(acc[mt][2][0]), "+f"(acc[mt][2][1]),
                      "+f"(acc[mt][2][2]), "+f"(acc[mt][2][3])
                    : "r"(a0), "r"(a1), "r"(a2), "r"(a3), "r"(bBx), "r"(bBy));
                asm volatile(
                    "mma.sync.aligned.m16n8k8.row.col.f32.tf32.tf32.f32 "
                    "{%0,%1,%2,%3}, {%4,%5,%6,%7}, {%8,%9}, {%0,%1,%2,%3};"
                    : "+f"(acc[mt][3][0]), "+f"(acc[mt][3][1]),
                      "+f"(acc[mt][3][2]), "+f"(acc[mt][3][3])
                    : "r"(a0), "r"(a1), "r"(a2), "r"(a3), "r"(bBz), "r"(bBw));
            }
        }
    };

    ldgTile(0);
    stsTile(0);
    __syncthreads();
    for (int i = 0; i < 8; i++) {
        if (i < 7) ldgTile((i + 1) * 32);
        compute(i & 1, i);
        if (i < 7) {
            __syncthreads();
            stsTile((i + 1) & 1);
            __syncthreads();
        }
    }

    #pragma unroll
    for (int mt = 0; mt < 4; mt++)
        #pragma unroll
        for (int nt = 0; nt < 4; nt++) {
            int row = m0 + wm * 64 + mt * 16 + gi;
            int pc = nb * 64 + wn * 16 + nt * 4 + ti;
            if (row < M)
                C[(size_t)row * 128 + pc] =
                    __floats2bfloat162_rn(acc[mt][nt][0], acc[mt][nt][1]);
            if (row + 8 < M)
                C[(size_t)(row + 8) * 128 + pc] =
                    __floats2bfloat162_rn(acc[mt][nt][2], acc[mt][nt][3]);
        }
}

// ---------------- gather helpers (packed f32x2; verified in round 6) ----------------
__device__ __forceinline__ unsigned long long bf2f2(unsigned u) {
    unsigned lo = u << 16, hi = u & 0xffff0000u;
    unsigned long long r;
    asm("mov.b64 %0, {%1,%2};" : "=l"(r) : "r"(lo), "r"(hi));
    return r;
}
__device__ __forceinline__ unsigned long long packf2(float w) {
    unsigned long long r;
    asm("mov.b64 %0, {%1,%1};" : "=l"(r) : "f"(w));
    return r;
}
__device__ __forceinline__ void fma2(unsigned long long& acc,
                                     unsigned long long v, unsigned long long w) {
    asm("fma.rn.f32x2 %0, %1, %2, %0;" : "+l"(acc) : "l"(v), "l"(w));
}
__device__ __forceinline__ void row_fma(const uint4* __restrict__ H, int s, int lane,
                                        unsigned long long w2, unsigned long long* acc) {
    uint4 v = H[(size_t)s * 32 + lane];
    fma2(acc[0], bf2f2(v.x), w2);
    fma2(acc[1], bf2f2(v.y), w2);
    fma2(acc[2], bf2f2(v.z), w2);
    fma2(acc[3], bf2f2(v.w), w2);
}

// ---- per-node gather: direct broadcast loads, unroll 4 ----
__device__ __forceinline__ void gather_node(const uint4* __restrict__ H,
        const int* __restrict__ rowstart, const int* __restrict__ csr,
        const float* __restrict__ dinv, const float* __restrict__ bias,
        int node, int lane, float di, float* res) {
    int r0 = rowstart[node], r1 = rowstart[node + 1];
    unsigned long long acc[4] = {0ull, 0ull, 0ull, 0ull};
    row_fma(H, node, lane, packf2(di), acc);   // self loop
    int e = r0;
    for (; e + 3 < r1; e += 4) {
        int s0 = csr[e], s1 = csr[e + 1], s2 = csr[e + 2], s3 = csr[e + 3];
        float w0 = dinv[s0], w1 = dinv[s1], w2 = dinv[s2], w3 = dinv[s3];
        row_fma(H, s0, lane, packf2(w0), acc);
        row_fma(H, s1, lane, packf2(w1), acc);
        row_fma(H, s2, lane, packf2(w2), acc);
        row_fma(H, s3, lane, packf2(w3), acc);
    }
    for (; e < r1; e++) {
        int s0 = csr[e];
        row_fma(H, s0, lane, packf2(dinv[s0]), acc);
    }
    float4 b0 = *(const float4*)(bias + lane * 8);
    float4 b1 = *(const float4*)(bias + lane * 8 + 4);
    float bb[8] = {b0.x, b0.y, b0.z, b0.w, b1.x, b1.y, b1.z, b1.w};
    #pragma unroll
    for (int jj = 0; jj < 4; jj++) {
        float x0, x1;
        asm("mov.b64 {%0,%1}, %2;" : "=f"(x0), "=f"(x1) : "l"(acc[jj]));
        res[2 * jj]     = fmaxf(fmaf(di, x0, bb[2 * jj]),     0.f);
        res[2 * jj + 1] = fmaxf(fmaf(di, x1, bb[2 * jj + 1]), 0.f);
    }
}

// ---------------- gather 1: write bf16 activations ----------------
__global__ void k_gather1(const uint4* __restrict__ H, uint4* __restrict__ out,
                          const int* __restrict__ rowstart, const int* __restrict__ csr,
                          const float* __restrict__ dinv,
                          const float* __restrict__ bias, int n) {
    int node = blockIdx.x * 8 + (threadIdx.x >> 5);
    if (node >= n) return;
    int lane = threadIdx.x & 31;
    float res[8];
    gather_node(H, rowstart, csr, dinv, bias, node, lane, dinv[node], res);
    __nv_bfloat162 r[4];
    #pragma unroll
    for (int j = 0; j < 4; j++)
        r[j] = __floats2bfloat162_rn(res[2 * j], res[2 * j + 1]);
    out[(size_t)node * 32 + lane] = *(uint4*)r;
}

// ---------------- gather 2: reduce directly into mean ----------------
__global__ void k_gather2(const uint4* __restrict__ H,
                          const int* __restrict__ rowstart, const int* __restrict__ csr,
                          const float* __restrict__ dinv,
                          const float* __restrict__ bias,
                          float* __restrict__ mean, int n) {
    __shared__ float sm[8][256];
    int warp = threadIdx.x >> 5;
    int lane = threadIdx.x & 31;
    int node = blockIdx.x * 8 + warp;
    float res[8] = {};
    if (node < n)
        gather_node(H, rowstart, csr, dinv, bias, node, lane, dinv[node], res);
    #pragma unroll
    for (int j = 0; j < 8; j++) sm[warp][lane * 8 + j] = res[j];
    __syncthreads();
    int c = threadIdx.x;
    float s = 0.f;
    #pragma unroll
    for (int w = 0; w < 8; w++) s += sm[w][c];
    atomicAdd(&mean[c], s);
}

// ---------------- MLP head ----------------
__global__ void k_head(const float* __restrict__ mean,
                       const float* __restrict__ fcW1, const float* __restrict__ fcb1,
                       const float* __restrict__ fcW2, const float* __restrict__ fcb2,
                       const float* __restrict__ fcW3, const float* __restrict__ fcb3,
                       float* __restrict__ out, int n) {
    __shared__ float g[256], h[256];
    int j = threadIdx.x;
    g[j] = fmaxf(mean[j] * (1.0f / (float)n), 0.f);
    __syncthreads();
    float s = fcb1[j];
    #pragma unroll 8
    for (int i = 0; i < 256; i++) s = fmaf(g[i], fcW1[i * 256 + j], s);
    h[j] = fmaxf(s, 0.f);
    __syncthreads();
    s = fcb2[j];
    #pragma unroll 8
    for (int i = 0; i < 256; i++) s = fmaf(h[i], fcW2[i * 256 + j], s);
    float g2 = fmaxf(s, 0.f);
    __syncthreads();
    g[j] = g2;
    __syncthreads();
    if (j < 64) {
        s = fcb3[j];
        #pragma unroll 8
        for (int i = 0; i < 256; i++) s = fmaf(g[i], fcW3[i * 64 + j], s);
        out[j] = s;
    }
}

extern "C" void kernel_launch(void* const* d_in, const int* in_sizes, int n_in,
                              void* d_out, int out_size) {
    const float* x    = (const float*)d_in[0];
    const int*   ei   = (const int*)  d_in[1];   // [2, E] int32
    const float* W1   = (const float*)d_in[2];
    const float* b1   = (const float*)d_in[3];
    const float* W2   = (const float*)d_in[4];
    const float* b2   = (const float*)d_in[5];
    const float* fcW1 = (const float*)d_in[6];
    const float* fcb1 = (const float*)d_in[7];
    const float* fcW2 = (const float*)d_in[8];
    const float* fcb2 = (const float*)d_in[9];
    const float* fcW3 = (const float*)d_in[10];
    const float* fcb3 = (const float*)d_in[11];
    float* out = (float*)d_out;

    int E = in_sizes[1] / 2;
    int N = in_sizes[0] / DIM;
    const int* src = ei;
    const int* dst = ei + E;

    __nv_bfloat16 *hbuf, *abuf;
    float *dinv, *mean, *wp1, *wp2;
    int *degi, *rowstart, *cursor, *csr;
    cudaGetSymbolAddress((void**)&hbuf, d_h);
    cudaGetSymbolAddress((void**)&abuf, d_a);
    cudaGetSymbolAddress((void**)&degi, d_degi);
    cudaGetSymbolAddress((void**)&dinv, d_dinv);
    cudaGetSymbolAddress((void**)&mean, d_mean);
    cudaGetSymbolAddress((void**)&rowstart, d_rowstart);
    cudaGetSymbolAddress((void**)&cursor, d_cursor);
    cudaGetSymbolAddress((void**)&csr, d_csr);
    cudaGetSymbolAddress((void**)&wp1, d_wp1);
    cudaGetSymbolAddress((void**)&wp2, d_wp2);

    // side stream + events (created once; host-side resources only)
    static cudaStream_t s_side = nullptr;
    static cudaEvent_t ev_fork = nullptr, ev_join = nullptr;
    if (s_side == nullptr) {
        cudaStreamCreateWithFlags(&s_side, cudaStreamNonBlocking);
        cudaEventCreateWithFlags(&ev_fork, cudaEventDisableTiming);
        cudaEventCreateWithFlags(&ev_join, cudaEventDisableTiming);
    }

    dim3 gg(2, (N + 127) / 128);
    unsigned gblocks = (unsigned)((N + 7) / 8);

    // ---- fork: W2 permute + CSR build on side stream, concurrent with GEMM-1 ----
    cudaEventRecord(ev_fork, 0);
    cudaStreamWaitEvent(s_side, ev_fork, 0);
    k_permB<<<256, 256, 0, s_side>>>(W2, wp2);
    cudaMemsetAsync(degi, 0, (size_t)N * sizeof(int), s_side);
    k_deg<<<(E + 255) / 256, 256, 0, s_side>>>(dst, E, degi);
    k_scan<<<1, 1024, 0, s_side>>>(degi, rowstart, cursor, dinv, N);
    k_fill<<<(E + 255) / 256, 256, 0, s_side>>>(src, dst, cursor, csr, E);
    cudaEventRecord(ev_join, s_side);

    // main stream: W1 permute, GEMM-1, mean clear
    cudaMemsetAsync(mean, 0, DIM * sizeof(float));
    k_permB<<<256, 256>>>(W1, wp1);
    k_gemm<false><<<gg, 256>>>(x, wp1, (__nv_bfloat162*)hbuf, N);

    // join before the gather needs the CSR (and before gemm2 needs wp2)
    cudaStreamWaitEvent(0, ev_join, 0);

    // ---- layer 1 aggregation ----
    k_gather1<<<gblocks, 256>>>((const uint4*)hbuf, (uint4*)abuf,
                                rowstart, csr, dinv, b1, N);
    // ---- layer 2 (mean fused into gather) ----
    k_gemm<true><<<gg, 256>>>(abuf, wp2, (__nv_bfloat162*)hbuf, N);
    k_gather2<<<gblocks, 256>>>((const uint4*)hbuf, rowstart, csr, dinv, b2,
                                mean, N);
    // ---- head ----
    k_head<<<1, 256>>>(mean, fcW1, fcb1, fcW2, fcb2, fcW3, fcb3, out, N);
}